// round 16
// baseline (speedup 1.0000x reference)
#include <cuda_runtime.h>
#include <math.h>

#define BB 64
#define NN 8732
#define CC 21
#define MM 16
#define BN (BB*NN)
#define TPB 256
#define NTILES (BN/TPB)          // 2183 exactly
#define TILE_F (TPB*CC)          // 5376 floats
#define TILE_V4 (TILE_F/4)       // 1344 float4
#define INVALID_PK 0x80000000

// ---- persistent scratch (no allocations; reset by K_B tail each run) ----
__device__ float        g_vbuf[BN];
__device__ unsigned int g_hist1[4096];
__device__ unsigned int g_h2c[4096];
__device__ float        g_h2s[4096];
__device__ double       g_posCe;
__device__ double       g_negHi;
__device__ double       g_bboxSum;
__device__ int          g_posCnt;
__device__ int          g_validCnt;
__device__ int          g_b0;
__device__ int          g_cntAbove1;
__device__ unsigned int g_ctrA, g_ctrB;

__device__ __forceinline__ float smooth_l1(float d) {
    float a = fabsf(d);
    return a < 1.0f ? 0.5f * d * d : a - 0.5f;
}

// ============ K_A: parse-inline tiled softmax + hist; tail = level-1 scan ======
__global__ void __launch_bounds__(TPB) k_main(const float* __restrict__ conf,
                                              const float* __restrict__ bboxOut,
                                              const float* __restrict__ target,
                                              const float* __restrict__ predBoxes) {
    __shared__ float        st[TILE_F];    // 21504 B
    __shared__ unsigned int sh[4096];      // 16384 B
    __shared__ int          spk[32];       // packed (globalAnchor<<8)|cls for <=2 batches
    __shared__ unsigned int ssum[256];
    __shared__ bool sLast;

    const int tid = threadIdx.x;
    const int bid = blockIdx.x;

    // --- blocks 0..63: batch-bid bbox loss + counts (warp 0) ---
    if (bid < BB && tid < 32) {
        bool valid = false, pos = false;
        double s = 0.0;
        if (tid < MM) {
            const float* t = target + bid * (1 + 6 * MM);
            int num = (int)t[0];
            const float* e = t + 1 + 6 * tid;
            int ci = (int)e[0];
            int k  = (int)e[5];
            valid = (tid < num);
            if (valid) {
                pos = (ci > 0);
                float tx1 = e[1], ty1 = e[2], tx2 = e[3], ty2 = e[4];
                const float* p = predBoxes + (size_t)k * 4;
                float pw = p[2] - p[0], ph = p[3] - p[1];
                float eb0 = ((tx1 + tx2) * 0.5f - (p[0] + p[2]) * 0.5f) / pw;
                float eb1 = ((ty1 + ty2) * 0.5f - (p[1] + p[3]) * 0.5f) / ph;
                float eb2 = logf((tx2 - tx1) / pw);
                float eb3 = logf((ty2 - ty1) / ph);
                const float* bo = bboxOut + ((size_t)bid * NN + (size_t)k) * 4;
                s = (double)(smooth_l1(bo[0] - eb0) + smooth_l1(bo[1] - eb1)
                           + smooth_l1(bo[2] - eb2) + smooth_l1(bo[3] - eb3));
            }
        }
        unsigned vmask = __ballot_sync(0xFFFFFFFFu, valid);
        unsigned pmask = __ballot_sync(0xFFFFFFFFu, pos);
#pragma unroll
        for (int off = 16; off > 0; off >>= 1)
            s += __shfl_down_sync(0xFFFFFFFFu, s, off);
        if (tid == 0) {
            atomicAdd(&g_validCnt, (int)__popc(vmask));
            atomicAdd(&g_posCnt,   (int)__popc(pmask));
            atomicAdd(&g_bboxSum,  s);
        }
    }

    // --- inline parse of the <=2 batches this tile touches (warp 1) ---
    const int iBase   = bid * TPB;
    const int b_first = iBase / NN;
    const int b_last  = (iBase + TPB - 1) / NN;
    if (tid >= 32 && tid < 64) {
        int j  = tid - 32;                 // 0..31
        int bb = b_first + (j >> 4);
        int m  = j & 15;
        int pk = INVALID_PK;
        if (bb <= b_last && bb < BB) {
            const float* t = target + bb * (1 + 6 * MM);
            int num = (int)t[0];
            if (m < num) {
                const float* e = t + 1 + 6 * m;
                int ci  = (int)e[0];
                int k   = (int)e[5];
                int cls = (ci > 0) ? ci : 0;
                pk = ((bb * NN + k) << 8) | cls;   // global anchor idx, 20 bits
            }
        }
        spk[j] = pk;
    }

    // zero smem hist
    for (int i = tid; i < 4096; i += TPB) sh[i] = 0u;

    // coalesced tile load
    const float4* src = (const float4*)(conf + (size_t)bid * TILE_F);
    for (int i = tid; i < TILE_V4; i += TPB)
        ((float4*)st)[i] = src[i];
    __syncthreads();

    // --- per-anchor softmax ---
    {
        const int i = iBase + tid;
        const float* row = st + tid * CC;   // stride 21: conflict-free
        float r[CC];
#pragma unroll
        for (int c = 0; c < CC; c++) r[c] = row[c];
        float mx = r[0];
#pragma unroll
        for (int c = 1; c < CC; c++) mx = fmaxf(mx, r[c]);
        float se = 0.0f;
#pragma unroll
        for (int c = 0; c < CC; c++) se += __expf(r[c] - mx);
        float logZ = mx + __logf(se);

        int cls = -1;
#pragma unroll
        for (int m = 0; m < 32; m++) {
            int p = spk[m];                          // broadcast read
            if ((p >> 8) == i) cls = p & 0xFF;       // invalid: negative, never == i
        }

        if (cls < 0) {
            float v = fmaxf(logZ - r[0], 0.0f);
            g_vbuf[i] = v;
            atomicAdd(&sh[__float_as_uint(v) >> 20], 1u);
        } else {
            g_vbuf[i] = 0.0f;
            if (cls > 0) atomicAdd(&g_posCe, (double)(logZ - r[cls]));
        }
    }
    __syncthreads();
    for (int i = tid; i < 4096; i += TPB) {
        unsigned int c = sh[i];
        if (c) atomicAdd(&g_hist1[i], c);
    }

    // --- last-block tail: level-1 suffix scan ---
    __threadfence();
    __syncthreads();
    if (tid == 0) sLast = (atomicAdd(&g_ctrA, 1u) == (unsigned)(gridDim.x - 1));
    __syncthreads();
    if (!sLast) return;

    unsigned int c[16];
    unsigned int s = 0;
#pragma unroll
    for (int j = 0; j < 16; j++) { c[j] = __ldcg(&g_hist1[tid * 16 + j]); s += c[j]; }
    ssum[tid] = s;
    __syncthreads();
    for (int off = 1; off < 256; off <<= 1) {
        unsigned int v = (tid + off < 256) ? ssum[tid + off] : 0u;
        __syncthreads();
        ssum[tid] += v;
        __syncthreads();
    }
    int K = 3 * g_posCnt;
    unsigned int e = (tid < 255) ? ssum[tid + 1] : 0u;
#pragma unroll
    for (int j = 15; j >= 0; j--) {
        if ((int)e < K && (int)(e + c[j]) >= K) { g_b0 = tid * 16 + j; g_cntAbove1 = (int)e; }
        e += c[j];
    }
    if (tid == 0 && (int)ssum[0] < K) { g_b0 = 0; g_cntAbove1 = (int)ssum[0]; }
}

// ============ K_B: pass2; tail = level-2 finalize + state reset ================
__global__ void __launch_bounds__(TPB) k_pass2(float* __restrict__ out) {
    __shared__ unsigned int ssum[256];
    __shared__ double sred[256];
    __shared__ bool sLast;

    const int tid = threadIdx.x;
    const int i = blockIdx.x * TPB + tid;
    const int b0 = g_b0;

    double hi = 0.0;
    if (i < BN) {
        float v = g_vbuf[i];
        unsigned int bits = __float_as_uint(v);
        if (bits != 0u) {
            int t12 = (int)(bits >> 20);
            if (t12 > b0) {
                hi = (double)v;
            } else if (t12 == b0) {
                unsigned int b2 = (bits >> 8) & 0xFFFu;
                atomicAdd(&g_h2c[b2], 1u);
                atomicAdd(&g_h2s[b2], v);
            }
        }
    }
    // warp-aggregated negHi atomic
#pragma unroll
    for (int off = 16; off > 0; off >>= 1)
        hi += __shfl_down_sync(0xFFFFFFFFu, hi, off);
    if ((tid & 31) == 0 && hi != 0.0) atomicAdd(&g_negHi, hi);

    // --- last-block tail ---
    __threadfence();
    __syncthreads();
    if (tid == 0) sLast = (atomicAdd(&g_ctrB, 1u) == (unsigned)(gridDim.x - 1));
    __syncthreads();
    if (!sLast) return;

    unsigned int c[16];
    float        bs[16];
    unsigned int s = 0;
#pragma unroll
    for (int j = 0; j < 16; j++) {
        c[j]  = __ldcg(&g_h2c[tid * 16 + j]);
        bs[j] = __ldcg(&g_h2s[tid * 16 + j]);
        s += c[j];
    }
    ssum[tid] = s;
    __syncthreads();
    for (int off = 1; off < 256; off <<= 1) {
        unsigned int v = (tid + off < 256) ? ssum[tid + off] : 0u;
        __syncthreads();
        ssum[tid] += v;
        __syncthreads();
    }

    int K = 3 * g_posCnt;
    long long r = (long long)K - (long long)g_cntAbove1;
    if (r < 0) r = 0;

    unsigned int e = (tid < 255) ? ssum[tid + 1] : 0u;
    double local = 0.0;
#pragma unroll
    for (int j = 15; j >= 0; j--) {
        unsigned int cj = c[j];
        if (cj) {
            long long rem = r - (long long)e;
            long long take = rem < 0 ? 0 : (rem > (long long)cj ? (long long)cj : rem);
            if (take > 0)
                local += (double)bs[j] * ((double)take / (double)cj);
        }
        e += cj;
    }
    sred[tid] = local;
    __syncthreads();
    for (int off = 128; off > 0; off >>= 1) {
        if (tid < off) sred[tid] += sred[tid + off];
        __syncthreads();
    }

    if (tid == 0) {
        double posCe    = __ldcg(&g_posCe);
        double negHi    = __ldcg(&g_negHi);
        double bboxSum  = __ldcg(&g_bboxSum);
        int    posCnt   = g_posCnt;
        int    validCnt = g_validCnt;

        double sneg = negHi + sred[0];
        long long selCnt = (long long)posCnt * 4;
        if (selCnt < 1) selCnt = 1;
        double conf_loss = (posCe + sneg) / (double)selCnt;
        long long denomB = 4LL * (long long)validCnt;
        if (denomB < 1) denomB = 1;
        double bbox_loss = bboxSum / (double)denomB;

        out[0] = (float)conf_loss;
        out[1] = (float)bbox_loss;

        // reset scalar state for the next execution
        g_posCe = 0.0; g_negHi = 0.0; g_bboxSum = 0.0;
        g_posCnt = 0;  g_validCnt = 0;
        g_ctrA = 0u;   g_ctrB = 0u;
    }
    __syncthreads();
    // reset histogram arrays for the next execution (256 threads x 16 each)
#pragma unroll
    for (int j = 0; j < 16; j++) {
        g_hist1[tid * 16 + j] = 0u;
        g_h2c[tid * 16 + j]   = 0u;
        g_h2s[tid * 16 + j]   = 0.0f;
    }
}

extern "C" void kernel_launch(void* const* d_in, const int* in_sizes, int n_in,
                              void* d_out, int out_size) {
    const float* conf   = (const float*)d_in[0];   // (B, N, C)
    const float* bbox   = (const float*)d_in[1];   // (B, N, 4)
    const float* target = (const float*)d_in[2];   // (B, 1+6M)
    const float* pred   = (const float*)d_in[3];   // (N, 4)
    float* out = (float*)d_out;

    k_main<<<NTILES, TPB>>>(conf, bbox, target, pred);
    k_pass2<<<NTILES, TPB>>>(out);
}